// round 10
// baseline (speedup 1.0000x reference)
#include <cuda_runtime.h>
#include <cstdint>

// DepConv3D R10: 2px x 8oc per thread, slice-pair f32x2 accumulators (32
// regs) with ALL 32 oc per CTA and __launch_bounds__(256,3) -> 24 warps/SM.
// Weights: [k][i][g] float4 slice-pair lines in smem, warp-uniform broadcast
// LDS. Features duplicated (f,f); gating = one 64-bit AND per (px,kx).

#define CCH 16
#define HH 512
#define WW 512
#define OCC 32
#define TW 32
#define TH 4
#define FT_ROWS 6
#define SPAIRS 34                         // pair s <-> gx = x0 + s - 1
#define SW_BYTES (9*16*16*16)             // 36864
#define SF_BYTES (CCH*FT_ROWS*SPAIRS*8)   // 26112
#define SD_INTS  (FT_ROWS*36)
#define SMEM_TOTAL (SW_BYTES + SF_BYTES + SD_INTS*4)   // 63840

typedef unsigned long long ull;

__device__ float4 g_wpack[9 * 16 * 16];

__global__ void pack_weights_kernel(const float* __restrict__ wgt)
{
    int idx = blockIdx.x * blockDim.x + threadIdx.x;   // (k*16+i)*16+g
    if (idx < 9 * 16 * 16) {
        int g = idx & 15;
        int i = (idx >> 4) & 15;
        int k = idx >> 8;
        int oc0 = 2 * g, oc1 = 2 * g + 1;
        float4 v;
        v.x = wgt[((oc0 * CCH + i) * 3 + 0) * 9 + k];   // W0[oc0]
        v.y = wgt[((oc0 * CCH + i) * 3 + 1) * 9 + k];   // W1[oc0]
        v.z = wgt[((oc1 * CCH + i) * 3 + 0) * 9 + k];   // W0[oc1]
        v.w = wgt[((oc1 * CCH + i) * 3 + 1) * 9 + k];   // W1[oc1]
        g_wpack[idx] = v;
    }
}

__global__ __launch_bounds__(256, 3)
void depconv3d_kernel(const float* __restrict__ feat,
                      const int*   __restrict__ depth,
                      float* __restrict__ out)
{
    extern __shared__ char smem[];
    float4* sW = (float4*)smem;                        // [k][i][g]
    float2* sF = (float2*)(smem + SW_BYTES);           // [i][r][s] dup (f,f)
    int*    sD = (int*)(smem + SW_BYTES + SF_BYTES);   // [r][s36]

    const int tx = threadIdx.x;        // 0..15 -> px base x0 + 2*tx
    const int ty = threadIdx.y;        // 0..3
    const int tz = threadIdx.z;        // 0..3  -> oc 8*tz..8*tz+7 (uniform)
    const int tid = tx + 16 * ty + 64 * tz;
    const int b  = blockIdx.z;
    const int y0 = blockIdx.y * TH;
    const int x0 = blockIdx.x * TW;

    // ---- stage packed weights (coalesced float4) ----
    #pragma unroll
    for (int it = 0; it < 9; it++)
        sW[tid + it * 256] = g_wpack[tid + it * 256];

    // ---- depth tile: s <-> gx = x0 + s - 1 ----
    for (int idx = tid; idx < SD_INTS; idx += 256) {
        int r = idx / 36, s = idx - r * 36;
        int gy = y0 + r - 1, gx = x0 + s - 1;
        int d = 0;
        if (gy >= 0 && gy < HH && gx >= 0 && gx < WW && s < SPAIRS)
            d = depth[(b * HH + gy) * WW + gx];
        sD[idx] = d;
    }

    // ---- feature tiles, duplicated (f,f) ----
    for (int idx = tid; idx < CCH * FT_ROWS * SPAIRS; idx += 256) {
        int s   = idx % SPAIRS;
        int rem = idx / SPAIRS;
        int r   = rem % FT_ROWS;
        int i   = rem / FT_ROWS;
        int gy = y0 + r - 1, gx = x0 + s - 1;
        float v = 0.f;
        if (gy >= 0 && gy < HH && gx >= 0 && gx < WW)
            v = feat[((size_t)(b * CCH + i) * HH + gy) * WW + gx];
        sF[idx] = make_float2(v, v);
    }
    __syncthreads();

    // ---- per-pixel 9-bit masks (A: dn==dc-1, B: dn==dc) ----
    unsigned mA[2], mB[2];
    #pragma unroll
    for (int p = 0; p < 2; p++) {
        int dc = sD[(ty + 1) * 36 + 2 * tx + p + 1];
        unsigned a = 0, bm = 0;
        #pragma unroll
        for (int k = 0; k < 9; k++) {
            int ky = k / 3, kx = k - ky * 3;
            int dn = sD[(ty + ky) * 36 + 2 * tx + p + kx];
            a  |= (unsigned)(dn == dc - 1) << k;
            bm |= (unsigned)(dn == dc)     << k;
        }
        mA[p] = a; mB[p] = bm;
    }

    ull acc[2][8];                      // [px][local oc], lanes = (sliceA, sliceB)
    #pragma unroll
    for (int p = 0; p < 2; p++)
        #pragma unroll
        for (int o = 0; o < 8; o++) acc[p][o] = 0ull;

    const unsigned fw = (unsigned)__cvta_generic_to_shared(sF);
    const unsigned ww = (unsigned)__cvta_generic_to_shared(sW) + (unsigned)(4 * tz) * 16u;

    #pragma unroll 1
    for (int ky = 0; ky < 3; ky++) {
        // gate words: M[kx][p] = (-A, -B) halves
        ull M[3][2];
        #pragma unroll
        for (int kx = 0; kx < 3; kx++)
            #pragma unroll
            for (int p = 0; p < 2; p++) {
                int k = ky * 3 + kx;
                unsigned lo = 0u - ((mA[p] >> k) & 1u);
                unsigned hi = 0u - ((mB[p] >> k) & 1u);
                M[kx][p] = ((ull)hi << 32) | lo;
            }

        const unsigned frow = fw + (unsigned)(((ty + ky) * SPAIRS + 2 * tx) * 8);

        #pragma unroll 2
        for (int i = 0; i < CCH; i++) {
            unsigned fa = frow + (unsigned)(i * FT_ROWS * SPAIRS * 8);
            ull P[4];
            asm("ld.shared.v2.b64 {%0,%1},[%2];" : "=l"(P[0]), "=l"(P[1]) : "r"(fa));
            asm("ld.shared.v2.b64 {%0,%1},[%2];" : "=l"(P[2]), "=l"(P[3]) : "r"(fa + 16));

            #pragma unroll
            for (int kx = 0; kx < 3; kx++) {
                ull G0 = P[kx]     & M[kx][0];
                ull G1 = P[kx + 1] & M[kx][1];
                unsigned wa = ww + (unsigned)(((ky * 3 + kx) * 16 + i) * 16) * 16u;
                #pragma unroll
                for (int j = 0; j < 4; j++) {
                    ull u, v;
                    asm("ld.shared.v2.b64 {%0,%1},[%2];"
                        : "=l"(u), "=l"(v) : "r"(wa + j * 16));   // g = 4*tz + j
                    asm("fma.rn.f32x2 %0,%1,%2,%0;" : "+l"(acc[0][2*j])   : "l"(G0), "l"(u));
                    asm("fma.rn.f32x2 %0,%1,%2,%0;" : "+l"(acc[0][2*j+1]) : "l"(G0), "l"(v));
                    asm("fma.rn.f32x2 %0,%1,%2,%0;" : "+l"(acc[1][2*j])   : "l"(G1), "l"(u));
                    asm("fma.rn.f32x2 %0,%1,%2,%0;" : "+l"(acc[1][2*j+1]) : "l"(G1), "l"(v));
                }
            }
        }
    }

    // ---- epilogue: out = sliceA + sliceB; float2 store (2 px) per oc ----
    const int gx = x0 + 2 * tx;
    const int gy = y0 + ty;
    #pragma unroll
    for (int o = 0; o < 8; o++) {
        float2 a0 = *reinterpret_cast<float2*>(&acc[0][o]);
        float2 a1 = *reinterpret_cast<float2*>(&acc[1][o]);
        float2 st = make_float2(a0.x + a0.y, a1.x + a1.y);
        size_t off = (((size_t)(b * OCC + 8 * tz + o) * HH + gy) * WW) + gx;
        *reinterpret_cast<float2*>(out + off) = st;
    }
}

extern "C" void kernel_launch(void* const* d_in, const int* in_sizes, int n_in,
                              void* d_out, int out_size)
{
    const float* feat  = (const float*)d_in[0];
    const int*   depth = (const int*)d_in[1];
    const float* wgt   = (const float*)d_in[2];
    float* out = (float*)d_out;

    cudaFuncSetAttribute(depconv3d_kernel,
                         cudaFuncAttributeMaxDynamicSharedMemorySize, SMEM_TOTAL);

    pack_weights_kernel<<<(9 * 16 * 16 + 255) / 256, 256>>>(wgt);

    dim3 block(16, 4, 4);
    dim3 grid(WW / TW, HH / TH, 4);
    depconv3d_kernel<<<grid, block, SMEM_TOTAL>>>(feat, depth, out);
}

// round 13
// speedup vs baseline: 1.6219x; 1.6219x over previous
#include <cuda_runtime.h>
#include <cstdint>

// DepConv3D R13: pixel-pair FFMA2 lanes, slice-summed accumulators,
// ky-PHASED dup-weight staging. 4px x 8oc per thread, acc = 16 ull = 32
// regs -> __launch_bounds__(256,3) = 24 warps/SM. Weights (w,w)-duplicated
// per depth slice; only the current ky's 24.6KB slice lives in smem
// ([i][kx][s][e], e=0..15 oc-pairs), restaged per ky. Features plain float
// tile; odd pixel-pairs packed with movs; gating = AND with packed masks.

#define CCH 16
#define HH 512
#define WW 512
#define OCC 32
#define TW 64
#define TH 4
#define SPITCH 68                        // floats per row; c <-> gx = x0+c-1
#define SWK_ENT (16*3*2*16)              // per-ky float4 entries = 1536 (24576 B)
#define SW_ENT  (3*SWK_ENT)              // 4608 total in global
#define SF_FLOATS (CCH*6*SPITCH)         // 6528
#define SD_INTS (6*SPITCH)               // 408
#define SMEM_TOTAL (SWK_ENT*16 + SF_FLOATS*4 + SD_INTS*4)   // 52320

typedef unsigned long long ull;

__device__ float4 g_wd[SW_ENT];

__global__ void pack_weights_kernel(const float* __restrict__ wgt)
{
    // idx = ((ky*16+i)*3+kx)*32 + s*16 + e
    int idx = blockIdx.x * blockDim.x + threadIdx.x;
    if (idx < SW_ENT) {
        int e  = idx & 15;
        int s  = (idx >> 4) & 1;
        int kx = (idx >> 5) % 3;
        int i  = (idx / 96) & 15;
        int ky = idx / 1536;
        int k = ky * 3 + kx;
        float w0 = wgt[(((2 * e)     * CCH + i) * 3 + s) * 9 + k];
        float w1 = wgt[(((2 * e + 1) * CCH + i) * 3 + s) * 9 + k];
        g_wd[idx] = make_float4(w0, w0, w1, w1);
    }
}

__global__ __launch_bounds__(256, 3)
void depconv3d_kernel(const float* __restrict__ feat,
                      const int*   __restrict__ depth,
                      float* __restrict__ out)
{
    extern __shared__ char smem[];
    float4* sWk = (float4*)smem;                         // current ky: [i][kx][s][e]
    float*  sF  = (float*)(smem + SWK_ENT * 16);         // [i][r][c]
    int*    sD  = (int*)(smem + SWK_ENT * 16 + SF_FLOATS * 4);

    const int tx = threadIdx.x;        // 0..15 -> px base x0 + 4*tx
    const int ty = threadIdx.y;        // 0..3
    const int tz = threadIdx.z;        // 0..3  -> oc 8*tz..8*tz+7 (uniform)
    const int tid = tx + 16 * ty + 64 * tz;
    const int b  = blockIdx.z;
    const int y0 = blockIdx.y * TH;
    const int x0 = blockIdx.x * TW;

    // ---- depth tile ----
    for (int idx = tid; idx < SD_INTS; idx += 256) {
        int r = idx / SPITCH, c = idx - r * SPITCH;
        int gy = y0 + r - 1, gx = x0 + c - 1;
        int d = 0;
        if (gy >= 0 && gy < HH && gx >= 0 && gx < WW && c < 66)
            d = depth[(b * HH + gy) * WW + gx];
        sD[idx] = d;
    }

    // ---- feature tiles (plain floats) ----
    for (int idx = tid; idx < SF_FLOATS; idx += 256) {
        int c   = idx % SPITCH;
        int rem = idx / SPITCH;
        int r   = rem % 6;
        int i   = rem / 6;
        int gy = y0 + r - 1, gx = x0 + c - 1;
        float v = 0.f;
        if (gy >= 0 && gy < HH && gx >= 0 && gx < WW && c < 66)
            v = feat[((size_t)(b * CCH + i) * HH + gy) * WW + gx];
        sF[idx] = v;
    }
    __syncthreads();

    // ---- per-pixel 9-bit masks (A: dn==dc-1, B: dn==dc) ----
    unsigned mA[4], mB[4];
    #pragma unroll
    for (int p = 0; p < 4; p++) {
        int dc = sD[(ty + 1) * SPITCH + 4 * tx + p + 1];
        unsigned a = 0, bm = 0;
        #pragma unroll
        for (int k = 0; k < 9; k++) {
            int ky = k / 3, kx = k - ky * 3;
            int dn = sD[(ty + ky) * SPITCH + 4 * tx + p + kx];
            a  |= (unsigned)(dn == dc - 1) << k;
            bm |= (unsigned)(dn == dc)     << k;
        }
        mA[p] = a; mB[p] = bm;
    }

    ull acc[2][8];                     // [pxpair q][local oc], lanes = (px2q, px2q+1)
    #pragma unroll
    for (int q = 0; q < 2; q++)
        #pragma unroll
        for (int o = 0; o < 8; o++) acc[q][o] = 0ull;

    const unsigned fw0 = (unsigned)__cvta_generic_to_shared(sF)
                       + (unsigned)((ty * SPITCH + 4 * tx) * 4);
    const unsigned ww0 = (unsigned)__cvta_generic_to_shared(sWk)
                       + (unsigned)(4 * tz) * 16u;      // e base = 4*tz

    #pragma unroll 1
    for (int ky = 0; ky < 3; ky++) {
        // ---- stage this ky's dup-weight slice (coalesced, 6 float4/thread) ----
        __syncthreads();               // prior ky's reads complete before overwrite
        #pragma unroll
        for (int it = 0; it < 6; it++)
            sWk[tid + it * 256] = g_wd[ky * SWK_ENT + tid + it * 256];
        __syncthreads();

        // gate words M[kx][q][s]: halves = (-bit(px 2q), -bit(px 2q+1))
        ull M[3][2][2];
        #pragma unroll
        for (int kx = 0; kx < 3; kx++)
            #pragma unroll
            for (int q = 0; q < 2; q++) {
                int k = ky * 3 + kx;
                unsigned aL = 0u - ((mA[2 * q]     >> k) & 1u);
                unsigned aH = 0u - ((mA[2 * q + 1] >> k) & 1u);
                unsigned bL = 0u - ((mB[2 * q]     >> k) & 1u);
                unsigned bH = 0u - ((mB[2 * q + 1] >> k) & 1u);
                M[kx][q][0] = ((ull)aH << 32) | aL;
                M[kx][q][1] = ((ull)bH << 32) | bL;
            }

        unsigned fa = fw0 + (unsigned)(ky * SPITCH * 4);
        unsigned wa = ww0;             // i stride = 96 entries = 1536 B

        #pragma unroll 1
        for (int i = 0; i < CCH; i++) {
            // floats f0..f5 at cols 4tx..4tx+5
            ull P01, P23, P45;
            asm("ld.shared.v2.b64 {%0,%1},[%2];" : "=l"(P01), "=l"(P23) : "r"(fa));
            asm("ld.shared.b64 %0,[%1];" : "=l"(P45) : "r"(fa + 16));
            unsigned c0, c1, c2, c3, c4, c5;
            asm("mov.b64 {%0,%1},%2;" : "=r"(c0), "=r"(c1) : "l"(P01));
            asm("mov.b64 {%0,%1},%2;" : "=r"(c2), "=r"(c3) : "l"(P23));
            asm("mov.b64 {%0,%1},%2;" : "=r"(c4), "=r"(c5) : "l"(P45));
            ull X12, X34;
            asm("mov.b64 %0,{%1,%2};" : "=l"(X12) : "r"(c1), "r"(c2));
            asm("mov.b64 %0,{%1,%2};" : "=l"(X34) : "r"(c3), "r"(c4));

            #pragma unroll
            for (int kx = 0; kx < 3; kx++) {
                ull Q0 = (kx == 0) ? P01 : (kx == 1) ? X12 : P23;
                ull Q1 = (kx == 0) ? P23 : (kx == 1) ? X34 : P45;
                ull GA0 = Q0 & M[kx][0][0];
                ull GA1 = Q1 & M[kx][1][0];
                ull GB0 = Q0 & M[kx][0][1];
                ull GB1 = Q1 & M[kx][1][1];
                #pragma unroll
                for (int j = 0; j < 4; j++) {     // slice A: kx*512 + j*16
                    ull u, v;
                    asm("ld.shared.v2.b64 {%0,%1},[%2];"
                        : "=l"(u), "=l"(v) : "r"(wa + (unsigned)(kx * 512 + j * 16)));
                    asm("fma.rn.f32x2 %0,%1,%2,%0;" : "+l"(acc[0][2*j])   : "l"(GA0), "l"(u));
                    asm("fma.rn.f32x2 %0,%1,%2,%0;" : "+l"(acc[0][2*j+1]) : "l"(GA0), "l"(v));
                    asm("fma.rn.f32x2 %0,%1,%2,%0;" : "+l"(acc[1][2*j])   : "l"(GA1), "l"(u));
                    asm("fma.rn.f32x2 %0,%1,%2,%0;" : "+l"(acc[1][2*j+1]) : "l"(GA1), "l"(v));
                }
                #pragma unroll
                for (int j = 0; j < 4; j++) {     // slice B: +256 B
                    ull u, v;
                    asm("ld.shared.v2.b64 {%0,%1},[%2];"
                        : "=l"(u), "=l"(v) : "r"(wa + (unsigned)(kx * 512 + 256 + j * 16)));
                    asm("fma.rn.f32x2 %0,%1,%2,%0;" : "+l"(acc[0][2*j])   : "l"(GB0), "l"(u));
                    asm("fma.rn.f32x2 %0,%1,%2,%0;" : "+l"(acc[0][2*j+1]) : "l"(GB0), "l"(v));
                    asm("fma.rn.f32x2 %0,%1,%2,%0;" : "+l"(acc[1][2*j])   : "l"(GB1), "l"(u));
                    asm("fma.rn.f32x2 %0,%1,%2,%0;" : "+l"(acc[1][2*j+1]) : "l"(GB1), "l"(v));
                }
            }
            fa += SPITCH * 6 * 4;       // next channel's tile
            wa += 1536;                 // next i block (96 entries * 16 B)
        }
    }

    // ---- epilogue: acc[q][o] = (out px2q, out px2q+1), oc = 8tz+o ----
    const int gx = x0 + 4 * tx;
    const int gy = y0 + ty;
    #pragma unroll
    for (int o = 0; o < 8; o++) {
        float2 q0 = *reinterpret_cast<float2*>(&acc[0][o]);
        float2 q1 = *reinterpret_cast<float2*>(&acc[1][o]);
        float4 st = make_float4(q0.x, q0.y, q1.x, q1.y);
        size_t off = (((size_t)(b * OCC + 8 * tz + o) * HH + gy) * WW) + gx;
        *reinterpret_cast<float4*>(out + off) = st;
    }
}

extern "C" void kernel_launch(void* const* d_in, const int* in_sizes, int n_in,
                              void* d_out, int out_size)
{
    const float* feat  = (const float*)d_in[0];
    const int*   depth = (const int*)d_in[1];
    const float* wgt   = (const float*)d_in[2];
    float* out = (float*)d_out;

    cudaFuncSetAttribute(depconv3d_kernel,
                         cudaFuncAttributeMaxDynamicSharedMemorySize, SMEM_TOTAL);

    pack_weights_kernel<<<(SW_ENT + 255) / 256, 256>>>(wgt);

    dim3 block(16, 4, 4);
    dim3 grid(WW / TW, HH / TH, 4);
    depconv3d_kernel<<<grid, block, SMEM_TOTAL>>>(feat, depth, out);
}